// round 11
// baseline (speedup 1.0000x reference)
#include <cuda_runtime.h>

// Problem constants
#define NB      2
#define NT      10
#define NC      8
#define NH      361
#define NW      720
#define LM      360
#define RR      5776       // NB*NC*NH
#define CHW     2079360    // NC*NH*NW
#define NOUT    4158720    // NB*CHW == RR*NW
#define HW      360        // folded longitude
#define KP      368        // padded K (360 -> 368)
#define FMLD    736        // g_Fm leading dim (2*KP)
#define NJ      181        // folded latitude nodes

// input element counts
#define SZ_X    41587200
#define SZ_A    8317440
#define SZ_LEG  46915560
#define SZ_WQ   361

// ---------------- scratch (device globals; device-code references only) ----
__device__ float g_xu  [NOUT];
__device__ float g_xe  [RR * KP];
__device__ float g_xo  [RR * KP];
__device__ float g_tblFE[360 * KP];
__device__ float g_tblFO[360 * KP];
__device__ float g_tblIE[KP * HW];
__device__ float g_tblIO[KP * HW];
__device__ float g_Ft  [NW * RR];        // rows: [0,180) ev-re, [180,360) ev-im, +360 odd
__device__ float g_FE  [360 * NJ * 32];  // folded even wf: [m][j][col]
__device__ float g_FO  [360 * NJ * 32];
__device__ float g_xsht[LM * LM * 32];   // [l][m][col], col=bc*2+ri
__device__ float g_ysht[LM * LM * 32];
__device__ float g_Fm  [RR * FMLD];
__device__ float g_Se  [RR * HW];        // longitude parity partial sums
__device__ float g_So  [RR * HW];

typedef unsigned long long u64;
__device__ __forceinline__ u64 ffma2(u64 a, u64 b, u64 c) {
    u64 d;
    asm("fma.rn.f32x2 %0, %1, %2, %3;" : "=l"(d) : "l"(a), "l"(b), "l"(c));
    return d;
}
__device__ __forceinline__ float lo32(u64 a) { return __uint_as_float((unsigned)(a & 0xffffffffull)); }
__device__ __forceinline__ float hi32(u64 a) { return __uint_as_float((unsigned)(a >> 32)); }

// ---------------- kernel 1: mean + center + longitude fold (float4) --------
__global__ void k_mean(const float* __restrict__ x) {
    int i = blockIdx.x * 256 + threadIdx.x;
    if (i >= RR * 90) return;
    int r = i / 90, w = (i - r * 90) * 4;
    int b = r / (NC * NH), rc = r - b * (NC * NH);
    const float* px = x + (size_t)b * NT * CHW + (size_t)rc * NW + w;
    float4 s1 = make_float4(0.f, 0.f, 0.f, 0.f);
    float4 s2 = make_float4(0.f, 0.f, 0.f, 0.f);
    float4 v1, v2;
#pragma unroll
    for (int t = 0; t < NT; t++) {
        v1 = *(const float4*)&px[(size_t)t * CHW];
        v2 = *(const float4*)&px[(size_t)t * CHW + 360];
        s1.x += v1.x; s1.y += v1.y; s1.z += v1.z; s1.w += v1.w;
        s2.x += v2.x; s2.y += v2.y; s2.z += v2.z; s2.w += v2.w;
    }
    const float inv = 1.0f / NT;
    float4 mu1 = make_float4(s1.x * inv, s1.y * inv, s1.z * inv, s1.w * inv);
    float4 mu2 = make_float4(s2.x * inv, s2.y * inv, s2.z * inv, s2.w * inv);
    float4 xc1 = make_float4(v1.x - mu1.x, v1.y - mu1.y, v1.z - mu1.z, v1.w - mu1.w);
    float4 xc2 = make_float4(v2.x - mu2.x, v2.y - mu2.y, v2.z - mu2.z, v2.w - mu2.w);
    size_t ro = (size_t)r * NW + w;
    *(float4*)&g_xu[ro]       = mu1;
    *(float4*)&g_xu[ro + 360] = mu2;
    *(float4*)&g_xe[(size_t)r * KP + w] =
        make_float4(xc1.x + xc2.x, xc1.y + xc2.y, xc1.z + xc2.z, xc1.w + xc2.w);
    *(float4*)&g_xo[(size_t)r * KP + w] =
        make_float4(xc1.x - xc2.x, xc1.y - xc2.y, xc1.z - xc2.z, xc1.w - xc2.w);
}

// ---------------- kernel 2: DFT tables --------------------------------------
__global__ void k_tables() {
    int i = blockIdx.x * 256 + threadIdx.x;
    if (i >= 360 * 360) return;
    int r = i / 360, w = i - r * 360;
    int mh = (r < 180) ? r : r - 180;
    bool isIm = (r >= 180);
    int me = 2 * mh, mo = 2 * mh + 1;
    float sve, cve, svo, cvo;
    sincospif(2.0f * (float)((me * w) % 720) / 720.0f, &sve, &cve);
    sincospif(2.0f * (float)((mo * w) % 720) / 720.0f, &svo, &cvo);
    const float sc = 6.28318530717958647692f / 720.0f;
    float kme = (me == 0) ? 1.0f : 2.0f;
    g_tblFE[r * KP + w] = isIm ? -sc * sve : sc * cve;
    g_tblFO[r * KP + w] = isIm ? -sc * svo : sc * cvo;
    g_tblIE[r * HW + w] = isIm ? -kme * sve : kme * cve;
    g_tblIO[r * HW + w] = isIm ? -2.0f * svo : 2.0f * cvo;
}

// ---------------- SGEMM: 128x128, BK=8 double-buffered, dup-A f32x2 --------
// A-tile stored DUPLICATED in smem: As2[k][2r]=As2[k][2r+1]=A[row r].
// Inner loop: 4x LDS.128 (A pairs) + 2x LDS.128 (B pairs) + 32 FFMA2, no packs.
template<int M, int N, int K, bool TB>
__device__ __forceinline__ void gemm_body(
    const float* __restrict__ A, int lda,
    const float* __restrict__ B, int ldb,
    float* __restrict__ C, int ldc)
{
    __shared__ float As2[2][8][260];   // 260 pad: 16B-aligned rows, 2-way STS max
    __shared__ float Bs[2][8][132];
    const int tid = threadIdx.x;
    const int bi = blockIdx.y * 128;
    const int bj = blockIdx.x * 128;
    const int ty = tid >> 4, tx = tid & 15;
    u64 acc[8][4];
#pragma unroll
    for (int u = 0; u < 8; u++)
#pragma unroll
        for (int v = 0; v < 4; v++) acc[u][v] = 0ull;

    const int arow = tid >> 3, acol = tid & 7;            // A: 32 rows x 8 k per pass
    const int bjj = TB ? (tid >> 3) : (tid & 127);
    const int bcc = TB ? (tid & 7)  : (tid >> 7);

    float ra[4], rb[4];
#pragma unroll
    for (int p = 0; p < 4; p++) {
        int gi = bi + arow + p * 32;
        ra[p] = (gi < M) ? A[(size_t)gi * lda + acol] : 0.f;
    }
#pragma unroll
    for (int p = 0; p < 4; p++) {
        if (TB) { int gj = bj + bjj + p * 32;
            rb[p] = (gj < N) ? B[(size_t)gj * ldb + bcc] : 0.f; }
        else { int gj = bj + bjj;
            rb[p] = (gj < N) ? B[(size_t)(bcc + 2 * p) * ldb + gj] : 0.f; }
    }
#pragma unroll
    for (int p = 0; p < 4; p++)
        *(float2*)&As2[0][acol][2 * (arow + p * 32)] = make_float2(ra[p], ra[p]);
#pragma unroll
    for (int p = 0; p < 4; p++) {
        if (TB) Bs[0][bcc][bjj + p * 32] = rb[p];
        else    Bs[0][bcc + 2 * p][bjj] = rb[p];
    }
    __syncthreads();

    const int NP = K / 8;
    for (int pp = 0; pp < NP; pp++) {
        int cur = pp & 1;
        if (pp + 1 < NP) {
            int k0 = (pp + 1) * 8;
#pragma unroll
            for (int p = 0; p < 4; p++) {
                int gi = bi + arow + p * 32;
                ra[p] = (gi < M) ? A[(size_t)gi * lda + k0 + acol] : 0.f;
            }
#pragma unroll
            for (int p = 0; p < 4; p++) {
                if (TB) { int gj = bj + bjj + p * 32;
                    rb[p] = (gj < N) ? B[(size_t)gj * ldb + k0 + bcc] : 0.f; }
                else { int gj = bj + bjj;
                    rb[p] = (gj < N) ? B[(size_t)(k0 + bcc + 2 * p) * ldb + gj] : 0.f; }
            }
        }
#pragma unroll
        for (int k = 0; k < 8; k++) {
            const float* ar = &As2[cur][k][16 * ty];
            ulonglong2 A0 = *(const ulonglong2*)(ar);
            ulonglong2 A1 = *(const ulonglong2*)(ar + 4);
            ulonglong2 A2 = *(const ulonglong2*)(ar + 8);
            ulonglong2 A3 = *(const ulonglong2*)(ar + 12);
            const float* br = &Bs[cur][k][8 * tx];
            ulonglong2 B0 = *(const ulonglong2*)(br);
            ulonglong2 B1 = *(const ulonglong2*)(br + 4);
            u64 ap[8] = {A0.x, A0.y, A1.x, A1.y, A2.x, A2.y, A3.x, A3.y};
            u64 bv[4] = {B0.x, B0.y, B1.x, B1.y};
#pragma unroll
            for (int u = 0; u < 8; u++) {
                acc[u][0] = ffma2(ap[u], bv[0], acc[u][0]);
                acc[u][1] = ffma2(ap[u], bv[1], acc[u][1]);
                acc[u][2] = ffma2(ap[u], bv[2], acc[u][2]);
                acc[u][3] = ffma2(ap[u], bv[3], acc[u][3]);
            }
        }
        if (pp + 1 < NP) {
#pragma unroll
            for (int p = 0; p < 4; p++)
                *(float2*)&As2[cur ^ 1][acol][2 * (arow + p * 32)] = make_float2(ra[p], ra[p]);
#pragma unroll
            for (int p = 0; p < 4; p++) {
                if (TB) Bs[cur ^ 1][bcc][bjj + p * 32] = rb[p];
                else    Bs[cur ^ 1][bcc + 2 * p][bjj] = rb[p];
            }
            __syncthreads();
        }
    }
#pragma unroll
    for (int u = 0; u < 8; u++) {
        int gi = bi + ty * 8 + u;
        if (gi >= M) continue;
#pragma unroll
        for (int v = 0; v < 4; v++) {
            int gj = bj + tx * 8 + v * 2;
            if (gj + 1 < N)      *(u64*)&C[(size_t)gi * ldc + gj] = acc[u][v];
            else if (gj < N)     C[(size_t)gi * ldc + gj] = lo32(acc[u][v]);
        }
    }
}

__global__ void __launch_bounds__(256, 2) k_gemm_fwd() {
    const float* Ap = blockIdx.z ? g_tblFO : g_tblFE;
    const float* Bp = blockIdx.z ? g_xo : g_xe;
    float* Cp = g_Ft + (blockIdx.z ? (size_t)360 * RR : 0);
    gemm_body<360, RR, KP, true>(Ap, KP, Bp, KP, Cp, RR);
}
__global__ void __launch_bounds__(256, 2) k_gemm_inv() {
    const float* Ap = g_Fm + (blockIdx.z ? KP : 0);
    const float* Bp = blockIdx.z ? g_tblIO : g_tblIE;
    float* Cp = blockIdx.z ? g_So : g_Se;
    gemm_body<RR, HW, KP, false>(Ap, FMLD, Bp, HW, Cp, HW);
}

// ---------------- fold F over latitude parity -------------------------------
__global__ void k_fold(const float* __restrict__ wq) {
    int i = blockIdx.x * 256 + threadIdx.x;
    if (i >= 360 * NJ * 32) return;
    int m = i / (NJ * 32);
    int rem = i - m * (NJ * 32);
    int j = rem >> 5, col = rem & 31;
    int bc = col >> 1, ri = col & 1;
    int row = (m & 1) * 360 + (m >> 1) + ri * 180;
    size_t base = (size_t)row * RR + bc * 361;
    float a = wq[j] * g_Ft[base + j];
    float E, O;
    if (j < 180) {
        float b = wq[360 - j] * g_Ft[base + 360 - j];
        E = a + b; O = a - b;
    } else { E = a; O = 0.f; }
    g_FE[i] = E; g_FO[i] = O;
}

// ---------------- Legendre analysis: 128l x 32col tiles, f32x2 --------------
__global__ void __launch_bounds__(256) k_ana(const float* __restrict__ leg)
{
    const int m  = blockIdx.x;
    const int l0 = blockIdx.y * 128;
    if (l0 + 128 <= m) return;

    __shared__ float legsT[32][132];
    __shared__ float fsC[32][68];
    const int tid = threadIdx.x;
    const int ty = tid >> 3, tx = tid & 7;
    u64 acc[2][4];
#pragma unroll
    for (int p = 0; p < 2; p++)
#pragma unroll
        for (int v = 0; v < 4; v++) acc[p][v] = 0ull;

    const int modd = m & 1;

    for (int j0 = 0; j0 < NJ; j0 += 32) {
#pragma unroll
        for (int p = 0; p < 16; p++) {
            int idx = tid + p * 256;
            int c = idx & 31, r = idx >> 5;
            int l = l0 + r, j = j0 + c;
            legsT[c][r] = (l < 360 && j < NJ)
                        ? leg[((size_t)l * NH + m) * NH + j] : 0.f;
        }
#pragma unroll
        for (int p = 0; p < 4; p++) {
            int idx = tid + p * 256;
            int col = idx & 31, jj = idx >> 5;
            int j = j0 + jj;
            float E = 0.f, O = 0.f;
            if (j < NJ) {
                size_t o = ((size_t)m * NJ + j) * 32 + col;
                E = g_FE[o]; O = g_FO[o];
            }
            fsC[jj][2 * col]     = modd ? O : E;
            fsC[jj][2 * col + 1] = modd ? E : O;
        }
        __syncthreads();
#pragma unroll 8
        for (int j = 0; j < 32; j++) {
            const u64* fr = (const u64*)&fsC[j][8 * tx];
            u64 b0 = fr[0], b1 = fr[1], b2 = fr[2], b3 = fr[3];
            u64 la = *(const u64*)&legsT[j][2 * ty];
            u64 lb = *(const u64*)&legsT[j][2 * ty + 64];
            acc[0][0] = ffma2(la, b0, acc[0][0]);
            acc[0][1] = ffma2(la, b1, acc[0][1]);
            acc[0][2] = ffma2(la, b2, acc[0][2]);
            acc[0][3] = ffma2(la, b3, acc[0][3]);
            acc[1][0] = ffma2(lb, b0, acc[1][0]);
            acc[1][1] = ffma2(lb, b1, acc[1][1]);
            acc[1][2] = ffma2(lb, b2, acc[1][2]);
            acc[1][3] = ffma2(lb, b3, acc[1][3]);
        }
        __syncthreads();
    }
#pragma unroll
    for (int p = 0; p < 2; p++) {
        int le = l0 + 2 * ty + 64 * p;
        int lo_ = le + 1;
        if (le < 360) {
            float4 f = make_float4(lo32(acc[p][0]), lo32(acc[p][1]),
                                   lo32(acc[p][2]), lo32(acc[p][3]));
            *(float4*)&g_xsht[((size_t)le * LM + m) * 32 + 4 * tx] = f;
        }
        if (lo_ < 360) {
            float4 f = make_float4(hi32(acc[p][0]), hi32(acc[p][1]),
                                   hi32(acc[p][2]), hi32(acc[p][3]));
            *(float4*)&g_xsht[((size_t)lo_ * LM + m) * 32 + 4 * tx] = f;
        }
    }
}

// ---------------- complex 8x8 channel mix + residual ------------------------
__global__ void __launch_bounds__(256) k_mix(
    const float* __restrict__ A, const float* __restrict__ Ai)
{
    const int l  = blockIdx.x;
    const int m0 = blockIdx.y * 16;
    __shared__ float xs[16][33];
    __shared__ float as[64][16];
    __shared__ float ais[64][16];
    const int tid = threadIdx.x;
#pragma unroll
    for (int p = 0; p < 2; p++) {
        int id = tid + p * 256;
        int dm = id >> 5, q = id & 31;
        int m = m0 + dm;
        xs[dm][q] = (m < 360) ? g_xsht[((size_t)l * LM + m) * 32 + q] : 0.f;
    }
#pragma unroll
    for (int p = 0; p < 4; p++) {
        int id = tid + p * 256;
        int cc = id >> 4, dm = id & 15;
        int m = m0 + dm;
        size_t o = ((size_t)cc * LM + l) * 361 + m;
        as[cc][dm]  = (m < 360) ? A[o]  : 0.f;
        ais[cc][dm] = (m < 360) ? Ai[o] : 0.f;
    }
    __syncthreads();
    int dm = tid & 15, bC = tid >> 4;
    int b = bC >> 3, Cq = bC & 7;
    int m = m0 + dm;
    float yr = xs[dm][(b * 8 + Cq) * 2];
    float yi = xs[dm][(b * 8 + Cq) * 2 + 1];
#pragma unroll
    for (int c = 0; c < 8; c++) {
        float arv = as[Cq * 8 + c][dm], aiv = ais[Cq * 8 + c][dm];
        float xr = xs[dm][(b * 8 + c) * 2], xi = xs[dm][(b * 8 + c) * 2 + 1];
        yr += arv * xr - aiv * xi;
        yi += arv * xi + aiv * xr;
    }
    if (m < 360) {
        size_t o = ((size_t)l * LM + m) * 32 + bC * 2;
        g_ysht[o]     = yr;
        g_ysht[o + 1] = yi;
    }
}

// ---------------- Legendre synthesis: parity fold, direct Fm writes ---------
__global__ void __launch_bounds__(256) k_syn(const float* __restrict__ leg)
{
    const int m  = blockIdx.x;
    const int jt = blockIdx.y;
    __shared__ float legs2[32][68];
    __shared__ float ys[32][36];
    const int tid = threadIdx.x;
    const int ty = tid >> 3, tx = tid & 7;
    float acc[2][2][4];
#pragma unroll
    for (int r = 0; r < 2; r++)
#pragma unroll
        for (int q = 0; q < 2; q++)
#pragma unroll
            for (int v = 0; v < 4; v++) acc[r][q][v] = 0.f;

    const int lstart = m & ~31;
    for (int l0 = lstart; l0 < 360; l0 += 32) {
#pragma unroll
        for (int p = 0; p < 8; p++) {
            int idx = tid + p * 256;
            int c = idx & 63, r = idx >> 6;
            int l = l0 + r, j = jt * 64 + c;
            legs2[r][c] = (l < 360 && j < NJ)
                        ? leg[((size_t)l * NH + m) * NH + j] : 0.f;
        }
#pragma unroll
        for (int p = 0; p < 4; p++) {
            int idx = tid + p * 256;
            int col = idx & 31, r = idx >> 5;
            int l = l0 + r;
            ys[r][col] = (l < 360) ? g_ysht[((size_t)l * LM + m) * 32 + col] : 0.f;
        }
        __syncthreads();
#pragma unroll 8
        for (int k = 0; k < 32; k++) {
            float4 yv = *(const float4*)&ys[k][4 * tx];
            float la = legs2[k][ty], lb = legs2[k][ty + 32];
            int q = k & 1;
            acc[0][q][0] += la * yv.x; acc[0][q][1] += la * yv.y;
            acc[0][q][2] += la * yv.z; acc[0][q][3] += la * yv.w;
            acc[1][q][0] += lb * yv.x; acc[1][q][1] += lb * yv.y;
            acc[1][q][2] += lb * yv.z; acc[1][q][3] += lb * yv.w;
        }
        __syncthreads();
    }
    const int pm = m & 1;
#pragma unroll
    for (int r = 0; r < 2; r++) {
        int j = jt * 64 + ty + 32 * r;
        if (j >= NJ) continue;
#pragma unroll
        for (int v = 0; v < 4; v++) {
            int col = 4 * tx + v;
            int bc = col >> 1, ri = col & 1;
            float se = acc[r][pm][v];
            float so = acc[r][1 - pm][v];
            size_t colm = (size_t)pm * KP + (m >> 1) + ri * 180;
            g_Fm[((size_t)(bc * 361 + j)) * FMLD + colm] = se + so;
            if (j < 180)
                g_Fm[((size_t)(bc * 361 + 360 - j)) * FMLD + colm] = se - so;
        }
    }
}

// ---------------- combine: unfold longitude + residual mean (float4) --------
__global__ void k_combine(float* __restrict__ out) {
    int i = blockIdx.x * 256 + threadIdx.x;
    if (i >= RR * 90) return;
    int r = i / 90, w = (i - r * 90) * 4;
    size_t si = (size_t)r * HW + w;
    float4 se = *(const float4*)&g_Se[si];
    float4 so = *(const float4*)&g_So[si];
    size_t o = (size_t)r * NW + w;
    float4 mu1 = *(const float4*)&g_xu[o];
    float4 mu2 = *(const float4*)&g_xu[o + 360];
    *(float4*)&out[o] = make_float4(se.x + so.x + mu1.x, se.y + so.y + mu1.y,
                                    se.z + so.z + mu1.z, se.w + so.w + mu1.w);
    *(float4*)&out[o + 360] = make_float4(se.x - so.x + mu2.x, se.y - so.y + mu2.y,
                                          se.z - so.z + mu2.z, se.w - so.w + mu2.w);
}

// ---------------- launch -----------------------------------------------------
extern "C" void kernel_launch(void* const* d_in, const int* in_sizes, int n_in,
                              void* d_out, int out_size) {
    const float* x = nullptr, *A = nullptr, *A_i = nullptr,
               *leg = nullptr, *wq = nullptr;
    for (int i = 0; i < n_in; i++) {
        int s = in_sizes[i];
        const float* p = (const float*)d_in[i];
        if (s == SZ_X)        x = p;
        else if (s == SZ_LEG) leg = p;
        else if (s == SZ_WQ)  wq = p;
        else if (s == SZ_A) { if (!A) A = p; else A_i = p; }
    }
    if (!x || !A || !A_i || !leg || !wq) {
        x = (const float*)d_in[0];  A = (const float*)d_in[1];
        A_i = (const float*)d_in[2]; leg = (const float*)d_in[3];
        wq = (const float*)d_in[4];
    }
    float* out = (float*)d_out;

    k_mean<<<(RR * 90 + 255) / 256, 256>>>(x);
    k_tables<<<(360 * 360 + 255) / 256, 256>>>();
    k_gemm_fwd<<<dim3((RR + 127) / 128, 3, 2), 256>>>();
    k_fold<<<(360 * NJ * 32 + 255) / 256, 256>>>(wq);
    k_ana<<<dim3(360, 3), 256>>>(leg);
    k_mix<<<dim3(360, 23), 256>>>(A, A_i);
    k_syn<<<dim3(360, 3), 256>>>(leg);
    k_gemm_inv<<<dim3(3, (RR + 127) / 128, 2), 256>>>();
    k_combine<<<(RR * 90 + 255) / 256, 256>>>(out);

    (void)out_size;
}

// round 15
// speedup vs baseline: 1.1950x; 1.1950x over previous
#include <cuda_runtime.h>
#include <cuda_bf16.h>
#include <cstdint>

// Problem constants
#define NB      2
#define NT      10
#define NC      8
#define NH      361
#define NW      720
#define LM      360
#define RR      5776       // NB*NC*NH
#define CHW     2079360    // NC*NH*NW
#define NOUT    4158720    // NB*CHW == RR*NW
#define HW      360        // folded longitude
#define KP      368        // padded K (23 x 16)
#define FMLD    736        // g_Fm leading dim (2*KP)
#define NJ      181        // folded latitude nodes

// input element counts
#define SZ_X    41587200
#define SZ_A    8317440
#define SZ_LEG  46915560
#define SZ_WQ   361

// ---------------- scratch (device globals; device-code references only) ----
__device__ float g_xu  [NOUT];
__device__ float g_tblIE[KP * HW];       // fp32 inverse tables (proven path)
__device__ float g_tblIO[KP * HW];
__device__ float g_Ft  [NW * RR];        // rows: [0,180) ev-re, [180,360) ev-im, +360 odd
__device__ float g_FE  [360 * NJ * 32];
__device__ float g_FO  [360 * NJ * 32];
__device__ float g_xsht[LM * LM * 32];
__device__ float g_ysht[LM * LM * 32];
__device__ float g_Fm  [RR * FMLD];
__device__ float g_Se  [RR * HW];
__device__ float g_So  [RR * HW];

// bf16 hi/lo split operands for FORWARD mma (aligned; bss zero => pads zero)
__device__ __align__(16) __nv_bfloat16 g_xeh[RR * KP],  g_xel[RR * KP];
__device__ __align__(16) __nv_bfloat16 g_xoh[RR * KP],  g_xol[RR * KP];
__device__ __align__(16) __nv_bfloat16 g_tfeh[360 * KP], g_tfel[360 * KP];
__device__ __align__(16) __nv_bfloat16 g_tfoh[360 * KP], g_tfol[360 * KP];

typedef unsigned long long u64;
__device__ __forceinline__ u64 ffma2(u64 a, u64 b, u64 c) {
    u64 d;
    asm("fma.rn.f32x2 %0, %1, %2, %3;" : "=l"(d) : "l"(a), "l"(b), "l"(c));
    return d;
}
__device__ __forceinline__ u64 pack2(float lo, float hi) {
    u64 r;
    asm("mov.b64 %0, {%1, %2};" : "=l"(r)
        : "r"(__float_as_uint(lo)), "r"(__float_as_uint(hi)));
    return r;
}
__device__ __forceinline__ float lo32(u64 a) { return __uint_as_float((unsigned)(a & 0xffffffffull)); }
__device__ __forceinline__ float hi32(u64 a) { return __uint_as_float((unsigned)(a >> 32)); }

__device__ __forceinline__ void bsplit(float v, __nv_bfloat16& h, __nv_bfloat16& l) {
    h = __float2bfloat16(v);
    l = __float2bfloat16(v - __bfloat162float(h));
}
__device__ __forceinline__ void split4(float4 v, u64& H, u64& L) {
    float f[4] = {v.x, v.y, v.z, v.w};
    H = 0; L = 0;
#pragma unroll
    for (int k = 0; k < 4; k++) {
        __nv_bfloat16 hb, lb; bsplit(f[k], hb, lb);
        H |= (u64)(*(unsigned short*)&hb) << (16 * k);
        L |= (u64)(*(unsigned short*)&lb) << (16 * k);
    }
}

// ---------------- mma.sync helpers (sm_80+ PTX) -----------------------------
__device__ __forceinline__ void mma16816(float* c, const uint32_t* a, const uint32_t* b) {
    asm volatile("mma.sync.aligned.m16n8k16.row.col.f32.bf16.bf16.f32 "
        "{%0,%1,%2,%3}, {%4,%5,%6,%7}, {%8,%9}, {%0,%1,%2,%3};"
        : "+f"(c[0]), "+f"(c[1]), "+f"(c[2]), "+f"(c[3])
        : "r"(a[0]), "r"(a[1]), "r"(a[2]), "r"(a[3]), "r"(b[0]), "r"(b[1]));
}
__device__ __forceinline__ void ldsm4(uint32_t* r, uint32_t addr) {
    asm volatile("ldmatrix.sync.aligned.m8n8.x4.shared.b16 {%0,%1,%2,%3}, [%4];"
        : "=r"(r[0]), "=r"(r[1]), "=r"(r[2]), "=r"(r[3]) : "r"(addr));
}
__device__ __forceinline__ uint32_t smem_u32(const void* p) {
    uint32_t a;
    asm("{ .reg .u64 t; cvta.to.shared.u64 t, %1; cvt.u32.u64 %0, t; }" : "=r"(a) : "l"(p));
    return a;
}

// ---------------- kernel 1: mean + center + longitude fold -> bf16 splits --
__global__ void k_mean(const float* __restrict__ x) {
    int i = blockIdx.x * 256 + threadIdx.x;
    if (i >= RR * 90) return;
    int r = i / 90, w = (i - r * 90) * 4;
    int b = r / (NC * NH), rc = r - b * (NC * NH);
    const float* px = x + (size_t)b * NT * CHW + (size_t)rc * NW + w;
    float4 s1 = make_float4(0.f, 0.f, 0.f, 0.f);
    float4 s2 = make_float4(0.f, 0.f, 0.f, 0.f);
    float4 v1, v2;
#pragma unroll
    for (int t = 0; t < NT; t++) {
        v1 = *(const float4*)&px[(size_t)t * CHW];
        v2 = *(const float4*)&px[(size_t)t * CHW + 360];
        s1.x += v1.x; s1.y += v1.y; s1.z += v1.z; s1.w += v1.w;
        s2.x += v2.x; s2.y += v2.y; s2.z += v2.z; s2.w += v2.w;
    }
    const float inv = 1.0f / NT;
    float4 mu1 = make_float4(s1.x * inv, s1.y * inv, s1.z * inv, s1.w * inv);
    float4 mu2 = make_float4(s2.x * inv, s2.y * inv, s2.z * inv, s2.w * inv);
    float4 xc1 = make_float4(v1.x - mu1.x, v1.y - mu1.y, v1.z - mu1.z, v1.w - mu1.w);
    float4 xc2 = make_float4(v2.x - mu2.x, v2.y - mu2.y, v2.z - mu2.z, v2.w - mu2.w);
    size_t ro = (size_t)r * NW + w;
    *(float4*)&g_xu[ro]       = mu1;
    *(float4*)&g_xu[ro + 360] = mu2;
    float4 xe = make_float4(xc1.x + xc2.x, xc1.y + xc2.y, xc1.z + xc2.z, xc1.w + xc2.w);
    float4 xo = make_float4(xc1.x - xc2.x, xc1.y - xc2.y, xc1.z - xc2.z, xc1.w - xc2.w);
    u64 H, L;
    size_t o = (size_t)r * KP + w;
    split4(xe, H, L); *(u64*)&g_xeh[o] = H; *(u64*)&g_xel[o] = L;
    split4(xo, H, L); *(u64*)&g_xoh[o] = H; *(u64*)&g_xol[o] = L;
}

// ---------------- kernel 2: DFT tables (bf16 fwd split + fp32 inverse) -----
__global__ void k_tables() {
    int i = blockIdx.x * 256 + threadIdx.x;
    if (i >= 360 * 360) return;
    int r = i / 360, w = i - r * 360;
    int mh = (r < 180) ? r : r - 180;
    bool isIm = (r >= 180);
    int me = 2 * mh, mo = 2 * mh + 1;
    float sve, cve, svo, cvo;
    sincospif(2.0f * (float)((me * w) % 720) / 720.0f, &sve, &cve);
    sincospif(2.0f * (float)((mo * w) % 720) / 720.0f, &svo, &cvo);
    const float sc = 6.28318530717958647692f / 720.0f;
    float kme = (me == 0) ? 1.0f : 2.0f;
    float vFE = isIm ? -sc * sve : sc * cve;
    float vFO = isIm ? -sc * svo : sc * cvo;
    __nv_bfloat16 h, l;
    bsplit(vFE, h, l); g_tfeh[r * KP + w] = h; g_tfel[r * KP + w] = l;
    bsplit(vFO, h, l); g_tfoh[r * KP + w] = h; g_tfol[r * KP + w] = l;
    g_tblIE[r * HW + w] = isIm ? -kme * sve : kme * cve;
    g_tblIO[r * HW + w] = isIm ? -2.0f * svo : 2.0f * cvo;
}

// ---------------- tensor GEMM (fwd only): C = (Ah+Al) x (Bh+Bl)^T -----------
#define PSTR  24                 // smem row stride (bf16)
#define PANEL (128 * PSTR)       // 3072 elements per panel
#define BUFE  (4 * PANEL)        // elements per buffer (Ah,Al,Bh,Bl)
#define SMEMT (2 * BUFE * 2)     // 49152 bytes

__device__ void tmma_body(
    const __nv_bfloat16* __restrict__ Ah, const __nv_bfloat16* __restrict__ Al, int lda,
    const __nv_bfloat16* __restrict__ Bh, const __nv_bfloat16* __restrict__ Bl, int ldb,
    float* __restrict__ C, int ldc, int M, int N)
{
    extern __shared__ __nv_bfloat16 smp[];
    const int tid = threadIdx.x, lane = tid & 31, wid = tid >> 5;
    const int bi = blockIdx.y * 128, bj = blockIdx.x * 128;
    const int wm = wid >> 2, wn = wid & 3;
    const uint32_t smb = smem_u32(smp);

    float acc[4][4][4];
#pragma unroll
    for (int a = 0; a < 4; a++)
#pragma unroll
        for (int b = 0; b < 4; b++)
#pragma unroll
            for (int c = 0; c < 4; c++) acc[a][b][c] = 0.f;

    const int lrow = tid >> 1, lseg = tid & 1;        // 128 rows x 2 segs of 8 bf16
    const int gi = bi + lrow, gj = bj + lrow;
    const int soff = lrow * PSTR + lseg * 8;          // elements; 16B-aligned

    const uint4 z4 = make_uint4(0u, 0u, 0u, 0u);
    uint4 vah = z4, val_ = z4, vbh = z4, vbl = z4;    // uint4 = 16B = 8 bf16
    if (gi < M) { size_t o = (size_t)gi * lda + lseg * 8; vah = *(const uint4*)(Ah + o); val_ = *(const uint4*)(Al + o); }
    if (gj < N) { size_t o = (size_t)gj * ldb + lseg * 8; vbh = *(const uint4*)(Bh + o); vbl = *(const uint4*)(Bl + o); }
    *(uint4*)&smp[0 * PANEL + soff] = vah;
    *(uint4*)&smp[1 * PANEL + soff] = val_;
    *(uint4*)&smp[2 * PANEL + soff] = vbh;
    *(uint4*)&smp[3 * PANEL + soff] = vbl;
    __syncthreads();

    const int grp = lane >> 3, l8 = lane & 7;
    const int aRow = (l8 + (grp & 1) * 8) * (PSTR * 2) + (grp >> 1) * 16;
    const int bRow = (l8 + (grp >> 1) * 8) * (PSTR * 2) + (grp & 1) * 16;

    const int NP = KP / 16;
    for (int pp = 0; pp < NP; pp++) {
        const int cur = pp & 1;
        if (pp + 1 < NP) {
            int k0 = (pp + 1) * 16;
            vah = val_ = vbh = vbl = z4;
            if (gi < M) { size_t o = (size_t)gi * lda + k0 + lseg * 8; vah = *(const uint4*)(Ah + o); val_ = *(const uint4*)(Al + o); }
            if (gj < N) { size_t o = (size_t)gj * ldb + k0 + lseg * 8; vbh = *(const uint4*)(Bh + o); vbl = *(const uint4*)(Bl + o); }
        }
        {
            const uint32_t base = smb + cur * (BUFE * 2);
            uint32_t ah[4][4], al[4][4];
#pragma unroll
            for (int mf = 0; mf < 4; mf++) {
                uint32_t ra = base + (wm * 64 + mf * 16) * (PSTR * 2) + aRow;
                ldsm4(ah[mf], ra);
                ldsm4(al[mf], ra + PANEL * 2);
            }
#pragma unroll
            for (int np = 0; np < 2; np++) {
                uint32_t rb = base + 2 * PANEL * 2 + (wn * 32 + np * 16) * (PSTR * 2) + bRow;
                uint32_t bh[4], bl[4];
                ldsm4(bh, rb);
                ldsm4(bl, rb + PANEL * 2);
#pragma unroll
                for (int sub = 0; sub < 2; sub++) {
                    int nf = np * 2 + sub;
#pragma unroll
                    for (int mf = 0; mf < 4; mf++) {
                        mma16816(acc[mf][nf], ah[mf], &bh[sub * 2]);
                        mma16816(acc[mf][nf], ah[mf], &bl[sub * 2]);
                        mma16816(acc[mf][nf], al[mf], &bh[sub * 2]);
                    }
                }
            }
        }
        if (pp + 1 < NP) {
            __nv_bfloat16* d = smp + (cur ^ 1) * BUFE;
            *(uint4*)&d[0 * PANEL + soff] = vah;
            *(uint4*)&d[1 * PANEL + soff] = val_;
            *(uint4*)&d[2 * PANEL + soff] = vbh;
            *(uint4*)&d[3 * PANEL + soff] = vbl;
            __syncthreads();
        }
    }

    const int er = lane >> 2, ec = (lane & 3) * 2;
#pragma unroll
    for (int mf = 0; mf < 4; mf++) {
#pragma unroll
        for (int nf = 0; nf < 4; nf++) {
            int r0 = bi + wm * 64 + mf * 16 + er;
            int c0 = bj + wn * 32 + nf * 8 + ec;
            if (c0 < N) {
                if (r0 < M)
                    *(float2*)&C[(size_t)r0 * ldc + c0] = make_float2(acc[mf][nf][0], acc[mf][nf][1]);
                if (r0 + 8 < M)
                    *(float2*)&C[(size_t)(r0 + 8) * ldc + c0] = make_float2(acc[mf][nf][2], acc[mf][nf][3]);
            }
        }
    }
}

__global__ void __launch_bounds__(256) k_tmma_fwd() {
    int z = blockIdx.z;
    tmma_body(z ? g_tfoh : g_tfeh, z ? g_tfol : g_tfel, KP,
              z ? g_xoh : g_xeh,   z ? g_xol : g_xel,   KP,
              g_Ft + (size_t)(z ? 360 : 0) * RR, RR, 360, RR);
}

// ---------------- R10 FFMA f32x2 SGEMM (inverse; proven) --------------------
template<int M, int N, int K, bool TB>
__device__ __forceinline__ void gemm_body(
    const float* __restrict__ A, int lda,
    const float* __restrict__ B, int ldb,
    float* __restrict__ C, int ldc)
{
    __shared__ float As[2][16][132];
    __shared__ float Bs[2][16][132];
    const int tid = threadIdx.x;
    const int bi = blockIdx.y * 128;
    const int bj = blockIdx.x * 128;
    const int ty = tid >> 4, tx = tid & 15;
    u64 acc[8][4];
#pragma unroll
    for (int u = 0; u < 8; u++)
#pragma unroll
        for (int v = 0; v < 4; v++) acc[u][v] = 0ull;

    const int arow = tid >> 4, acol = tid & 15;
    const int bjj = TB ? (tid >> 4) : (tid & 127);
    const int bcc = TB ? (tid & 15) : (tid >> 7);

    float ra[8], rb[8];
#pragma unroll
    for (int p = 0; p < 8; p++) {
        int gi = bi + arow + p * 16;
        ra[p] = (gi < M) ? A[(size_t)gi * lda + acol] : 0.f;
    }
#pragma unroll
    for (int p = 0; p < 8; p++) {
        if (TB) { int gj = bj + bjj + p * 16;
            rb[p] = (gj < N) ? B[(size_t)gj * ldb + bcc] : 0.f; }
        else { int gj = bj + bjj;
            rb[p] = (gj < N) ? B[(size_t)(bcc + 2 * p) * ldb + gj] : 0.f; }
    }
#pragma unroll
    for (int p = 0; p < 8; p++) As[0][acol][arow + p * 16] = ra[p];
#pragma unroll
    for (int p = 0; p < 8; p++) {
        if (TB) Bs[0][bcc][bjj + p * 16] = rb[p];
        else    Bs[0][bcc + 2 * p][bjj] = rb[p];
    }
    __syncthreads();

    const int NP = K / 16;
    for (int pp = 0; pp < NP; pp++) {
        int cur = pp & 1;
        if (pp + 1 < NP) {
            int k0 = (pp + 1) * 16;
#pragma unroll
            for (int p = 0; p < 8; p++) {
                int gi = bi + arow + p * 16;
                ra[p] = (gi < M) ? A[(size_t)gi * lda + k0 + acol] : 0.f;
            }
#pragma unroll
            for (int p = 0; p < 8; p++) {
                if (TB) { int gj = bj + bjj + p * 16;
                    rb[p] = (gj < N) ? B[(size_t)gj * ldb + k0 + bcc] : 0.f; }
                else { int gj = bj + bjj;
                    rb[p] = (gj < N) ? B[(size_t)(k0 + bcc + 2 * p) * ldb + gj] : 0.f; }
            }
        }
#pragma unroll
        for (int k = 0; k < 16; k++) {
            float4 a0 = *(const float4*)&As[cur][k][ty * 8];
            float4 a1 = *(const float4*)&As[cur][k][ty * 8 + 4];
            const u64* pb = (const u64*)&Bs[cur][k][tx * 8];
            u64 b0 = pb[0], b1 = pb[1], b2 = pb[2], b3 = pb[3];
            u64 ap[8];
            ap[0] = pack2(a0.x, a0.x); ap[1] = pack2(a0.y, a0.y);
            ap[2] = pack2(a0.z, a0.z); ap[3] = pack2(a0.w, a0.w);
            ap[4] = pack2(a1.x, a1.x); ap[5] = pack2(a1.y, a1.y);
            ap[6] = pack2(a1.z, a1.z); ap[7] = pack2(a1.w, a1.w);
#pragma unroll
            for (int u = 0; u < 8; u++) {
                acc[u][0] = ffma2(ap[u], b0, acc[u][0]);
                acc[u][1] = ffma2(ap[u], b1, acc[u][1]);
                acc[u][2] = ffma2(ap[u], b2, acc[u][2]);
                acc[u][3] = ffma2(ap[u], b3, acc[u][3]);
            }
        }
        if (pp + 1 < NP) {
#pragma unroll
            for (int p = 0; p < 8; p++) As[cur ^ 1][acol][arow + p * 16] = ra[p];
#pragma unroll
            for (int p = 0; p < 8; p++) {
                if (TB) Bs[cur ^ 1][bcc][bjj + p * 16] = rb[p];
                else    Bs[cur ^ 1][bcc + 2 * p][bjj] = rb[p];
            }
            __syncthreads();
        }
    }
#pragma unroll
    for (int u = 0; u < 8; u++) {
        int gi = bi + ty * 8 + u;
        if (gi >= M) continue;
#pragma unroll
        for (int v = 0; v < 4; v++) {
            int gj = bj + tx * 8 + v * 2;
            if (gj + 1 < N)      *(u64*)&C[(size_t)gi * ldc + gj] = acc[u][v];
            else if (gj < N)     C[(size_t)gi * ldc + gj] = lo32(acc[u][v]);
        }
    }
}

__global__ void __launch_bounds__(256, 2) k_gemm_inv() {
    const float* Ap = g_Fm + (blockIdx.z ? KP : 0);
    const float* Bp = blockIdx.z ? g_tblIO : g_tblIE;
    float* Cp = blockIdx.z ? g_So : g_Se;
    gemm_body<RR, HW, KP, false>(Ap, FMLD, Bp, HW, Cp, HW);
}

// ---------------- fold F over latitude parity -------------------------------
__global__ void k_fold(const float* __restrict__ wq) {
    int i = blockIdx.x * 256 + threadIdx.x;
    if (i >= 360 * NJ * 32) return;
    int m = i / (NJ * 32);
    int rem = i - m * (NJ * 32);
    int j = rem >> 5, col = rem & 31;
    int bc = col >> 1, ri = col & 1;
    int row = (m & 1) * 360 + (m >> 1) + ri * 180;
    size_t base = (size_t)row * RR + bc * 361;
    float a = wq[j] * g_Ft[base + j];
    float E, O;
    if (j < 180) {
        float b = wq[360 - j] * g_Ft[base + 360 - j];
        E = a + b; O = a - b;
    } else { E = a; O = 0.f; }
    g_FE[i] = E; g_FO[i] = O;
}

// ---------------- Legendre analysis: 128l x 32col tiles, f32x2 --------------
__global__ void __launch_bounds__(256) k_ana(const float* __restrict__ leg)
{
    const int m  = blockIdx.x;
    const int l0 = blockIdx.y * 128;
    if (l0 + 128 <= m) return;

    __shared__ float legsT[32][132];
    __shared__ float fsC[32][68];
    const int tid = threadIdx.x;
    const int ty = tid >> 3, tx = tid & 7;
    u64 acc[2][4];
#pragma unroll
    for (int p = 0; p < 2; p++)
#pragma unroll
        for (int v = 0; v < 4; v++) acc[p][v] = 0ull;

    const int modd = m & 1;

    for (int j0 = 0; j0 < NJ; j0 += 32) {
#pragma unroll
        for (int p = 0; p < 16; p++) {
            int idx = tid + p * 256;
            int c = idx & 31, r = idx >> 5;
            int l = l0 + r, j = j0 + c;
            legsT[c][r] = (l < 360 && j < NJ)
                        ? leg[((size_t)l * NH + m) * NH + j] : 0.f;
        }
#pragma unroll
        for (int p = 0; p < 4; p++) {
            int idx = tid + p * 256;
            int col = idx & 31, jj = idx >> 5;
            int j = j0 + jj;
            float E = 0.f, O = 0.f;
            if (j < NJ) {
                size_t o = ((size_t)m * NJ + j) * 32 + col;
                E = g_FE[o]; O = g_FO[o];
            }
            fsC[jj][2 * col]     = modd ? O : E;
            fsC[jj][2 * col + 1] = modd ? E : O;
        }
        __syncthreads();
#pragma unroll 8
        for (int j = 0; j < 32; j++) {
            const u64* fr = (const u64*)&fsC[j][8 * tx];
            u64 b0 = fr[0], b1 = fr[1], b2 = fr[2], b3 = fr[3];
            u64 la = *(const u64*)&legsT[j][2 * ty];
            u64 lb = *(const u64*)&legsT[j][2 * ty + 64];
            acc[0][0] = ffma2(la, b0, acc[0][0]);
            acc[0][1] = ffma2(la, b1, acc[0][1]);
            acc[0][2] = ffma2(la, b2, acc[0][2]);
            acc[0][3] = ffma2(la, b3, acc[0][3]);
            acc[1][0] = ffma2(lb, b0, acc[1][0]);
            acc[1][1] = ffma2(lb, b1, acc[1][1]);
            acc[1][2] = ffma2(lb, b2, acc[1][2]);
            acc[1][3] = ffma2(lb, b3, acc[1][3]);
        }
        __syncthreads();
    }
#pragma unroll
    for (int p = 0; p < 2; p++) {
        int le = l0 + 2 * ty + 64 * p;
        int lo_ = le + 1;
        if (le < 360) {
            float4 f = make_float4(lo32(acc[p][0]), lo32(acc[p][1]),
                                   lo32(acc[p][2]), lo32(acc[p][3]));
            *(float4*)&g_xsht[((size_t)le * LM + m) * 32 + 4 * tx] = f;
        }
        if (lo_ < 360) {
            float4 f = make_float4(hi32(acc[p][0]), hi32(acc[p][1]),
                                   hi32(acc[p][2]), hi32(acc[p][3]));
            *(float4*)&g_xsht[((size_t)lo_ * LM + m) * 32 + 4 * tx] = f;
        }
    }
}

// ---------------- complex 8x8 channel mix + residual ------------------------
__global__ void __launch_bounds__(256) k_mix(
    const float* __restrict__ A, const float* __restrict__ Ai)
{
    const int l  = blockIdx.x;
    const int m0 = blockIdx.y * 16;
    __shared__ float xs[16][33];
    __shared__ float as[64][16];
    __shared__ float ais[64][16];
    const int tid = threadIdx.x;
#pragma unroll
    for (int p = 0; p < 2; p++) {
        int id = tid + p * 256;
        int dm = id >> 5, q = id & 31;
        int m = m0 + dm;
        xs[dm][q] = (m < 360) ? g_xsht[((size_t)l * LM + m) * 32 + q] : 0.f;
    }
#pragma unroll
    for (int p = 0; p < 4; p++) {
        int id = tid + p * 256;
        int cc = id >> 4, dm = id & 15;
        int m = m0 + dm;
        size_t o = ((size_t)cc * LM + l) * 361 + m;
        as[cc][dm]  = (m < 360) ? A[o]  : 0.f;
        ais[cc][dm] = (m < 360) ? Ai[o] : 0.f;
    }
    __syncthreads();
    int dm = tid & 15, bC = tid >> 4;
    int b = bC >> 3, Cq = bC & 7;
    int m = m0 + dm;
    float yr = xs[dm][(b * 8 + Cq) * 2];
    float yi = xs[dm][(b * 8 + Cq) * 2 + 1];
#pragma unroll
    for (int c = 0; c < 8; c++) {
        float arv = as[Cq * 8 + c][dm], aiv = ais[Cq * 8 + c][dm];
        float xr = xs[dm][(b * 8 + c) * 2], xi = xs[dm][(b * 8 + c) * 2 + 1];
        yr += arv * xr - aiv * xi;
        yi += arv * xi + aiv * xr;
    }
    if (m < 360) {
        size_t o = ((size_t)l * LM + m) * 32 + bC * 2;
        g_ysht[o]     = yr;
        g_ysht[o + 1] = yi;
    }
}

// ---------------- Legendre synthesis: parity fold, direct Fm writes ---------
__global__ void __launch_bounds__(256) k_syn(const float* __restrict__ leg)
{
    const int m  = blockIdx.x;
    const int jt = blockIdx.y;
    __shared__ float legs2[32][68];
    __shared__ float ys[32][36];
    const int tid = threadIdx.x;
    const int ty = tid >> 3, tx = tid & 7;
    float acc[2][2][4];
#pragma unroll
    for (int r = 0; r < 2; r++)
#pragma unroll
        for (int q = 0; q < 2; q++)
#pragma unroll
            for (int v = 0; v < 4; v++) acc[r][q][v] = 0.f;

    const int lstart = m & ~31;
    for (int l0 = lstart; l0 < 360; l0 += 32) {
#pragma unroll
        for (int p = 0; p < 8; p++) {
            int idx = tid + p * 256;
            int c = idx & 63, r = idx >> 6;
            int l = l0 + r, j = jt * 64 + c;
            legs2[r][c] = (l < 360 && j < NJ)
                        ? leg[((size_t)l * NH + m) * NH + j] : 0.f;
        }
#pragma unroll
        for (int p = 0; p < 4; p++) {
            int idx = tid + p * 256;
            int col = idx & 31, r = idx >> 5;
            int l = l0 + r;
            ys[r][col] = (l < 360) ? g_ysht[((size_t)l * LM + m) * 32 + col] : 0.f;
        }
        __syncthreads();
#pragma unroll 8
        for (int k = 0; k < 32; k++) {
            float4 yv = *(const float4*)&ys[k][4 * tx];
            float la = legs2[k][ty], lb = legs2[k][ty + 32];
            int q = k & 1;
            acc[0][q][0] += la * yv.x; acc[0][q][1] += la * yv.y;
            acc[0][q][2] += la * yv.z; acc[0][q][3] += la * yv.w;
            acc[1][q][0] += lb * yv.x; acc[1][q][1] += lb * yv.y;
            acc[1][q][2] += lb * yv.z; acc[1][q][3] += lb * yv.w;
        }
        __syncthreads();
    }
    const int pm = m & 1;
#pragma unroll
    for (int r = 0; r < 2; r++) {
        int j = jt * 64 + ty + 32 * r;
        if (j >= NJ) continue;
#pragma unroll
        for (int v = 0; v < 4; v++) {
            int col = 4 * tx + v;
            int bc = col >> 1, ri = col & 1;
            float se = acc[r][pm][v];
            float so = acc[r][1 - pm][v];
            size_t colm = (size_t)pm * KP + (m >> 1) + ri * 180;
            g_Fm[((size_t)(bc * 361 + j)) * FMLD + colm] = se + so;
            if (j < 180)
                g_Fm[((size_t)(bc * 361 + 360 - j)) * FMLD + colm] = se - so;
        }
    }
}

// ---------------- combine: unfold longitude + residual mean (float4) --------
__global__ void k_combine(float* __restrict__ out) {
    int i = blockIdx.x * 256 + threadIdx.x;
    if (i >= RR * 90) return;
    int r = i / 90, w = (i - r * 90) * 4;
    size_t si = (size_t)r * HW + w;
    float4 se = *(const float4*)&g_Se[si];
    float4 so = *(const float4*)&g_So[si];
    size_t o = (size_t)r * NW + w;
    float4 mu1 = *(const float4*)&g_xu[o];
    float4 mu2 = *(const float4*)&g_xu[o + 360];
    *(float4*)&out[o] = make_float4(se.x + so.x + mu1.x, se.y + so.y + mu1.y,
                                    se.z + so.z + mu1.z, se.w + so.w + mu1.w);
    *(float4*)&out[o + 360] = make_float4(se.x - so.x + mu2.x, se.y - so.y + mu2.y,
                                          se.z - so.z + mu2.z, se.w - so.w + mu2.w);
}

// ---------------- launch -----------------------------------------------------
extern "C" void kernel_launch(void* const* d_in, const int* in_sizes, int n_in,
                              void* d_out, int out_size) {
    const float* x = nullptr, *A = nullptr, *A_i = nullptr,
               *leg = nullptr, *wq = nullptr;
    for (int i = 0; i < n_in; i++) {
        int s = in_sizes[i];
        const float* p = (const float*)d_in[i];
        if (s == SZ_X)        x = p;
        else if (s == SZ_LEG) leg = p;
        else if (s == SZ_WQ)  wq = p;
        else if (s == SZ_A) { if (!A) A = p; else A_i = p; }
    }
    if (!x || !A || !A_i || !leg || !wq) {
        x = (const float*)d_in[0];  A = (const float*)d_in[1];
        A_i = (const float*)d_in[2]; leg = (const float*)d_in[3];
        wq = (const float*)d_in[4];
    }
    float* out = (float*)d_out;

    static bool attr_set = false;
    if (!attr_set) {
        cudaFuncSetAttribute(k_tmma_fwd, cudaFuncAttributeMaxDynamicSharedMemorySize, SMEMT);
        attr_set = true;
    }

    k_mean<<<(RR * 90 + 255) / 256, 256>>>(x);
    k_tables<<<(360 * 360 + 255) / 256, 256>>>();
    k_tmma_fwd<<<dim3(46, 3, 2), 256, SMEMT>>>();
    k_fold<<<(360 * NJ * 32 + 255) / 256, 256>>>(wq);
    k_ana<<<dim3(360, 3), 256>>>(leg);
    k_mix<<<dim3(360, 23), 256>>>(A, A_i);
    k_syn<<<dim3(360, 3), 256>>>(leg);
    k_gemm_inv<<<dim3(3, (RR + 127) / 128, 2), 256>>>();
    k_combine<<<(RR * 90 + 255) / 256, 256>>>(out);

    (void)out_size;
}

// round 16
// speedup vs baseline: 1.2643x; 1.0580x over previous
#include <cuda_runtime.h>
#include <cuda_bf16.h>
#include <cstdint>

// Problem constants
#define NB      2
#define NT      10
#define NC      8
#define NH      361
#define NW      720
#define LM      360
#define RR      5776       // NB*NC*NH
#define CHW     2079360    // NC*NH*NW
#define NOUT    4158720    // NB*CHW == RR*NW
#define HW      360        // folded longitude
#define KP      368        // padded K (23 x 16)
#define FMLD    736        // g_Fm leading dim (2*KP)
#define NJ      181        // folded latitude nodes

// input element counts
#define SZ_X    41587200
#define SZ_A    8317440
#define SZ_LEG  46915560
#define SZ_WQ   361

// ---------------- scratch (device globals; device-code references only) ----
__device__ float g_xu  [NOUT];
__device__ float g_Ft  [NW * RR];        // rows: [0,180) ev-re, [180,360) ev-im, +360 odd
__device__ float g_FE  [360 * NJ * 32];
__device__ float g_FO  [360 * NJ * 32];
__device__ float g_xsht[LM * LM * 32];
__device__ float g_ysht[LM * LM * 32];
__device__ float g_Fm  [RR * FMLD];
__device__ float g_Se  [RR * HW];
__device__ float g_So  [RR * HW];

// bf16 hi/lo split operands (aligned; bss zero => pads zero)
__device__ __align__(16) __nv_bfloat16 g_xeh[RR * KP],  g_xel[RR * KP];
__device__ __align__(16) __nv_bfloat16 g_xoh[RR * KP],  g_xol[RR * KP];
__device__ __align__(16) __nv_bfloat16 g_tfeh[360 * KP], g_tfel[360 * KP];
__device__ __align__(16) __nv_bfloat16 g_tfoh[360 * KP], g_tfol[360 * KP];
__device__ __align__(16) __nv_bfloat16 g_tieh[360 * KP], g_tiel[360 * KP];  // TRANSPOSED [w][k]
__device__ __align__(16) __nv_bfloat16 g_tioh[360 * KP], g_tiol[360 * KP];
__device__ __align__(16) __nv_bfloat16 g_fmh[RR * FMLD], g_fml[RR * FMLD];

typedef unsigned long long u64;
__device__ __forceinline__ u64 ffma2(u64 a, u64 b, u64 c) {
    u64 d;
    asm("fma.rn.f32x2 %0, %1, %2, %3;" : "=l"(d) : "l"(a), "l"(b), "l"(c));
    return d;
}
__device__ __forceinline__ float lo32(u64 a) { return __uint_as_float((unsigned)(a & 0xffffffffull)); }
__device__ __forceinline__ float hi32(u64 a) { return __uint_as_float((unsigned)(a >> 32)); }

__device__ __forceinline__ void bsplit(float v, __nv_bfloat16& h, __nv_bfloat16& l) {
    h = __float2bfloat16(v);
    l = __float2bfloat16(v - __bfloat162float(h));
}
__device__ __forceinline__ void split4(float4 v, u64& H, u64& L) {
    float f[4] = {v.x, v.y, v.z, v.w};
    H = 0; L = 0;
#pragma unroll
    for (int k = 0; k < 4; k++) {
        __nv_bfloat16 hb, lb; bsplit(f[k], hb, lb);
        H |= (u64)(*(unsigned short*)&hb) << (16 * k);
        L |= (u64)(*(unsigned short*)&lb) << (16 * k);
    }
}

// ---------------- mma.sync helpers (sm_80+ PTX) -----------------------------
__device__ __forceinline__ void mma16816(float* c, const uint32_t* a, const uint32_t* b) {
    asm volatile("mma.sync.aligned.m16n8k16.row.col.f32.bf16.bf16.f32 "
        "{%0,%1,%2,%3}, {%4,%5,%6,%7}, {%8,%9}, {%0,%1,%2,%3};"
        : "+f"(c[0]), "+f"(c[1]), "+f"(c[2]), "+f"(c[3])
        : "r"(a[0]), "r"(a[1]), "r"(a[2]), "r"(a[3]), "r"(b[0]), "r"(b[1]));
}
__device__ __forceinline__ void ldsm4(uint32_t* r, uint32_t addr) {
    asm volatile("ldmatrix.sync.aligned.m8n8.x4.shared.b16 {%0,%1,%2,%3}, [%4];"
        : "=r"(r[0]), "=r"(r[1]), "=r"(r[2]), "=r"(r[3]) : "r"(addr));
}
__device__ __forceinline__ uint32_t smem_u32(const void* p) {
    uint32_t a;
    asm("{ .reg .u64 t; cvta.to.shared.u64 t, %1; cvt.u32.u64 %0, t; }" : "=r"(a) : "l"(p));
    return a;
}

// ---------------- kernel 1: mean + center + longitude fold -> bf16 splits --
__global__ void k_mean(const float* __restrict__ x) {
    int i = blockIdx.x * 256 + threadIdx.x;
    if (i >= RR * 90) return;
    int r = i / 90, w = (i - r * 90) * 4;
    int b = r / (NC * NH), rc = r - b * (NC * NH);
    const float* px = x + (size_t)b * NT * CHW + (size_t)rc * NW + w;
    float4 s1 = make_float4(0.f, 0.f, 0.f, 0.f);
    float4 s2 = make_float4(0.f, 0.f, 0.f, 0.f);
    float4 v1, v2;
#pragma unroll
    for (int t = 0; t < NT; t++) {
        v1 = *(const float4*)&px[(size_t)t * CHW];
        v2 = *(const float4*)&px[(size_t)t * CHW + 360];
        s1.x += v1.x; s1.y += v1.y; s1.z += v1.z; s1.w += v1.w;
        s2.x += v2.x; s2.y += v2.y; s2.z += v2.z; s2.w += v2.w;
    }
    const float inv = 1.0f / NT;
    float4 mu1 = make_float4(s1.x * inv, s1.y * inv, s1.z * inv, s1.w * inv);
    float4 mu2 = make_float4(s2.x * inv, s2.y * inv, s2.z * inv, s2.w * inv);
    float4 xc1 = make_float4(v1.x - mu1.x, v1.y - mu1.y, v1.z - mu1.z, v1.w - mu1.w);
    float4 xc2 = make_float4(v2.x - mu2.x, v2.y - mu2.y, v2.z - mu2.z, v2.w - mu2.w);
    size_t ro = (size_t)r * NW + w;
    *(float4*)&g_xu[ro]       = mu1;
    *(float4*)&g_xu[ro + 360] = mu2;
    float4 xe = make_float4(xc1.x + xc2.x, xc1.y + xc2.y, xc1.z + xc2.z, xc1.w + xc2.w);
    float4 xo = make_float4(xc1.x - xc2.x, xc1.y - xc2.y, xc1.z - xc2.z, xc1.w - xc2.w);
    u64 H, L;
    size_t o = (size_t)r * KP + w;
    split4(xe, H, L); *(u64*)&g_xeh[o] = H; *(u64*)&g_xel[o] = L;
    split4(xo, H, L); *(u64*)&g_xoh[o] = H; *(u64*)&g_xol[o] = L;
}

// ---------------- kernel 2: DFT tables (bf16 splits; inverse transposed) ---
__global__ void k_tables() {
    int i = blockIdx.x * 256 + threadIdx.x;
    if (i >= 360 * 360) return;
    int r = i / 360, w = i - r * 360;
    int mh = (r < 180) ? r : r - 180;
    bool isIm = (r >= 180);
    int me = 2 * mh, mo = 2 * mh + 1;
    float sve, cve, svo, cvo;
    sincospif(2.0f * (float)((me * w) % 720) / 720.0f, &sve, &cve);
    sincospif(2.0f * (float)((mo * w) % 720) / 720.0f, &svo, &cvo);
    const float sc = 6.28318530717958647692f / 720.0f;
    float kme = (me == 0) ? 1.0f : 2.0f;
    float vFE = isIm ? -sc * sve : sc * cve;
    float vFO = isIm ? -sc * svo : sc * cvo;
    float vIE = isIm ? -kme * sve : kme * cve;
    float vIO = isIm ? -2.0f * svo : 2.0f * cvo;
    __nv_bfloat16 h, l;
    bsplit(vFE, h, l); g_tfeh[r * KP + w] = h; g_tfel[r * KP + w] = l;
    bsplit(vFO, h, l); g_tfoh[r * KP + w] = h; g_tfol[r * KP + w] = l;
    bsplit(vIE, h, l); g_tieh[w * KP + r] = h; g_tiel[w * KP + r] = l;
    bsplit(vIO, h, l); g_tioh[w * KP + r] = h; g_tiol[w * KP + r] = l;
}

// ---------------- split g_Fm (fp32) -> bf16 hi/lo (same layout) -------------
__global__ void k_split() {
    int i = blockIdx.x * 256 + threadIdx.x;
    if (i >= RR * 368) return;
    int r = i / 368, c2 = (i - r * 368) * 2;
    size_t o = (size_t)r * FMLD + c2;
    float v0 = g_Fm[o], v1 = g_Fm[o + 1];
    __nv_bfloat16 h0, l0, h1, l1;
    bsplit(v0, h0, l0); bsplit(v1, h1, l1);
    *(__nv_bfloat162*)&g_fmh[o] = __nv_bfloat162(h0, h1);
    *(__nv_bfloat162*)&g_fml[o] = __nv_bfloat162(l0, l1);
}

// ---------------- tensor GEMM: C[M,N] = (Ah+Al)[M,K] x (Bh+Bl)[N,K]^T -------
#define PSTR  24                 // smem row stride (bf16)
#define PANEL (128 * PSTR)       // 3072 elements per panel
#define BUFE  (4 * PANEL)        // elements per buffer (Ah,Al,Bh,Bl)
#define SMEMT (2 * BUFE * 2)     // 49152 bytes

__device__ void tmma_body(
    const __nv_bfloat16* __restrict__ Ah, const __nv_bfloat16* __restrict__ Al, int lda,
    const __nv_bfloat16* __restrict__ Bh, const __nv_bfloat16* __restrict__ Bl, int ldb,
    float* __restrict__ C, int ldc, int M, int N)
{
    extern __shared__ __nv_bfloat16 smp[];
    const int tid = threadIdx.x, lane = tid & 31, wid = tid >> 5;
    const int bi = blockIdx.y * 128, bj = blockIdx.x * 128;
    const int wm = wid >> 2, wn = wid & 3;
    const uint32_t smb = smem_u32(smp);

    float acc[4][4][4];
#pragma unroll
    for (int a = 0; a < 4; a++)
#pragma unroll
        for (int b = 0; b < 4; b++)
#pragma unroll
            for (int c = 0; c < 4; c++) acc[a][b][c] = 0.f;

    const int lrow = tid >> 1, lseg = tid & 1;        // 128 rows x 2 segs of 8 bf16
    const int gi = bi + lrow, gj = bj + lrow;
    const int soff = lrow * PSTR + lseg * 8;          // elements; 16B-aligned

    const uint4 z4 = make_uint4(0u, 0u, 0u, 0u);
    uint4 vah = z4, val_ = z4, vbh = z4, vbl = z4;    // uint4 = 16B = 8 bf16
    if (gi < M) { size_t o = (size_t)gi * lda + lseg * 8; vah = *(const uint4*)(Ah + o); val_ = *(const uint4*)(Al + o); }
    if (gj < N) { size_t o = (size_t)gj * ldb + lseg * 8; vbh = *(const uint4*)(Bh + o); vbl = *(const uint4*)(Bl + o); }
    *(uint4*)&smp[0 * PANEL + soff] = vah;
    *(uint4*)&smp[1 * PANEL + soff] = val_;
    *(uint4*)&smp[2 * PANEL + soff] = vbh;
    *(uint4*)&smp[3 * PANEL + soff] = vbl;
    __syncthreads();

    const int grp = lane >> 3, l8 = lane & 7;
    const int aRow = (l8 + (grp & 1) * 8) * (PSTR * 2) + (grp >> 1) * 16;
    const int bRow = (l8 + (grp >> 1) * 8) * (PSTR * 2) + (grp & 1) * 16;

    const int NP = KP / 16;
    for (int pp = 0; pp < NP; pp++) {
        const int cur = pp & 1;
        if (pp + 1 < NP) {
            int k0 = (pp + 1) * 16;
            vah = val_ = vbh = vbl = z4;
            if (gi < M) { size_t o = (size_t)gi * lda + k0 + lseg * 8; vah = *(const uint4*)(Ah + o); val_ = *(const uint4*)(Al + o); }
            if (gj < N) { size_t o = (size_t)gj * ldb + k0 + lseg * 8; vbh = *(const uint4*)(Bh + o); vbl = *(const uint4*)(Bl + o); }
        }
        {
            const uint32_t base = smb + cur * (BUFE * 2);
            uint32_t ah[4][4], al[4][4];
#pragma unroll
            for (int mf = 0; mf < 4; mf++) {
                uint32_t ra = base + (wm * 64 + mf * 16) * (PSTR * 2) + aRow;
                ldsm4(ah[mf], ra);
                ldsm4(al[mf], ra + PANEL * 2);
            }
#pragma unroll
            for (int np = 0; np < 2; np++) {
                uint32_t rb = base + 2 * PANEL * 2 + (wn * 32 + np * 16) * (PSTR * 2) + bRow;
                uint32_t bh[4], bl[4];
                ldsm4(bh, rb);
                ldsm4(bl, rb + PANEL * 2);
#pragma unroll
                for (int sub = 0; sub < 2; sub++) {
                    int nf = np * 2 + sub;
#pragma unroll
                    for (int mf = 0; mf < 4; mf++) {
                        mma16816(acc[mf][nf], ah[mf], &bh[sub * 2]);
                        mma16816(acc[mf][nf], ah[mf], &bl[sub * 2]);
                        mma16816(acc[mf][nf], al[mf], &bh[sub * 2]);
                    }
                }
            }
        }
        if (pp + 1 < NP) {
            __nv_bfloat16* d = smp + (cur ^ 1) * BUFE;
            *(uint4*)&d[0 * PANEL + soff] = vah;
            *(uint4*)&d[1 * PANEL + soff] = val_;
            *(uint4*)&d[2 * PANEL + soff] = vbh;
            *(uint4*)&d[3 * PANEL + soff] = vbl;
            __syncthreads();
        }
    }

    const int er = lane >> 2, ec = (lane & 3) * 2;
#pragma unroll
    for (int mf = 0; mf < 4; mf++) {
#pragma unroll
        for (int nf = 0; nf < 4; nf++) {
            int r0 = bi + wm * 64 + mf * 16 + er;
            int c0 = bj + wn * 32 + nf * 8 + ec;
            if (c0 < N) {
                if (r0 < M)
                    *(float2*)&C[(size_t)r0 * ldc + c0] = make_float2(acc[mf][nf][0], acc[mf][nf][1]);
                if (r0 + 8 < M)
                    *(float2*)&C[(size_t)(r0 + 8) * ldc + c0] = make_float2(acc[mf][nf][2], acc[mf][nf][3]);
            }
        }
    }
}

__global__ void __launch_bounds__(256) k_tmma_fwd() {
    int z = blockIdx.z;
    tmma_body(z ? g_tfoh : g_tfeh, z ? g_tfol : g_tfel, KP,
              z ? g_xoh : g_xeh,   z ? g_xol : g_xel,   KP,
              g_Ft + (size_t)(z ? 360 : 0) * RR, RR, 360, RR);
}
__global__ void __launch_bounds__(256) k_tmma_inv() {
    int z = blockIdx.z;
    tmma_body(g_fmh + (size_t)z * KP, g_fml + (size_t)z * KP, FMLD,
              z ? g_tioh : g_tieh, z ? g_tiol : g_tiel, KP,
              z ? g_So : g_Se, HW, RR, 360);
}

// ---------------- fold F over latitude parity -------------------------------
__global__ void k_fold(const float* __restrict__ wq) {
    int i = blockIdx.x * 256 + threadIdx.x;
    if (i >= 360 * NJ * 32) return;
    int m = i / (NJ * 32);
    int rem = i - m * (NJ * 32);
    int j = rem >> 5, col = rem & 31;
    int bc = col >> 1, ri = col & 1;
    int row = (m & 1) * 360 + (m >> 1) + ri * 180;
    size_t base = (size_t)row * RR + bc * 361;
    float a = wq[j] * g_Ft[base + j];
    float E, O;
    if (j < 180) {
        float b = wq[360 - j] * g_Ft[base + 360 - j];
        E = a + b; O = a - b;
    } else { E = a; O = 0.f; }
    g_FE[i] = E; g_FO[i] = O;
}

// ---------------- Legendre analysis: 128l x 32col tiles, f32x2 --------------
__global__ void __launch_bounds__(256) k_ana(const float* __restrict__ leg)
{
    const int m  = blockIdx.x;
    const int l0 = blockIdx.y * 128;
    if (l0 + 128 <= m) return;

    __shared__ float legsT[32][132];
    __shared__ float fsC[32][68];
    const int tid = threadIdx.x;
    const int ty = tid >> 3, tx = tid & 7;
    u64 acc[2][4];
#pragma unroll
    for (int p = 0; p < 2; p++)
#pragma unroll
        for (int v = 0; v < 4; v++) acc[p][v] = 0ull;

    const int modd = m & 1;

    for (int j0 = 0; j0 < NJ; j0 += 32) {
#pragma unroll
        for (int p = 0; p < 16; p++) {
            int idx = tid + p * 256;
            int c = idx & 31, r = idx >> 5;
            int l = l0 + r, j = j0 + c;
            legsT[c][r] = (l < 360 && j < NJ)
                        ? leg[((size_t)l * NH + m) * NH + j] : 0.f;
        }
#pragma unroll
        for (int p = 0; p < 4; p++) {
            int idx = tid + p * 256;
            int col = idx & 31, jj = idx >> 5;
            int j = j0 + jj;
            float E = 0.f, O = 0.f;
            if (j < NJ) {
                size_t o = ((size_t)m * NJ + j) * 32 + col;
                E = g_FE[o]; O = g_FO[o];
            }
            fsC[jj][2 * col]     = modd ? O : E;
            fsC[jj][2 * col + 1] = modd ? E : O;
        }
        __syncthreads();
#pragma unroll 8
        for (int j = 0; j < 32; j++) {
            const u64* fr = (const u64*)&fsC[j][8 * tx];
            u64 b0 = fr[0], b1 = fr[1], b2 = fr[2], b3 = fr[3];
            u64 la = *(const u64*)&legsT[j][2 * ty];
            u64 lb = *(const u64*)&legsT[j][2 * ty + 64];
            acc[0][0] = ffma2(la, b0, acc[0][0]);
            acc[0][1] = ffma2(la, b1, acc[0][1]);
            acc[0][2] = ffma2(la, b2, acc[0][2]);
            acc[0][3] = ffma2(la, b3, acc[0][3]);
            acc[1][0] = ffma2(lb, b0, acc[1][0]);
            acc[1][1] = ffma2(lb, b1, acc[1][1]);
            acc[1][2] = ffma2(lb, b2, acc[1][2]);
            acc[1][3] = ffma2(lb, b3, acc[1][3]);
        }
        __syncthreads();
    }
#pragma unroll
    for (int p = 0; p < 2; p++) {
        int le = l0 + 2 * ty + 64 * p;
        int lo_ = le + 1;
        if (le < 360) {
            float4 f = make_float4(lo32(acc[p][0]), lo32(acc[p][1]),
                                   lo32(acc[p][2]), lo32(acc[p][3]));
            *(float4*)&g_xsht[((size_t)le * LM + m) * 32 + 4 * tx] = f;
        }
        if (lo_ < 360) {
            float4 f = make_float4(hi32(acc[p][0]), hi32(acc[p][1]),
                                   hi32(acc[p][2]), hi32(acc[p][3]));
            *(float4*)&g_xsht[((size_t)lo_ * LM + m) * 32 + 4 * tx] = f;
        }
    }
}

// ---------------- complex 8x8 channel mix + residual ------------------------
__global__ void __launch_bounds__(256) k_mix(
    const float* __restrict__ A, const float* __restrict__ Ai)
{
    const int l  = blockIdx.x;
    const int m0 = blockIdx.y * 16;
    __shared__ float xs[16][33];
    __shared__ float as[64][16];
    __shared__ float ais[64][16];
    const int tid = threadIdx.x;
#pragma unroll
    for (int p = 0; p < 2; p++) {
        int id = tid + p * 256;
        int dm = id >> 5, q = id & 31;
        int m = m0 + dm;
        xs[dm][q] = (m < 360) ? g_xsht[((size_t)l * LM + m) * 32 + q] : 0.f;
    }
#pragma unroll
    for (int p = 0; p < 4; p++) {
        int id = tid + p * 256;
        int cc = id >> 4, dm = id & 15;
        int m = m0 + dm;
        size_t o = ((size_t)cc * LM + l) * 361 + m;
        as[cc][dm]  = (m < 360) ? A[o]  : 0.f;
        ais[cc][dm] = (m < 360) ? Ai[o] : 0.f;
    }
    __syncthreads();
    int dm = tid & 15, bC = tid >> 4;
    int b = bC >> 3, Cq = bC & 7;
    int m = m0 + dm;
    float yr = xs[dm][(b * 8 + Cq) * 2];
    float yi = xs[dm][(b * 8 + Cq) * 2 + 1];
#pragma unroll
    for (int c = 0; c < 8; c++) {
        float arv = as[Cq * 8 + c][dm], aiv = ais[Cq * 8 + c][dm];
        float xr = xs[dm][(b * 8 + c) * 2], xi = xs[dm][(b * 8 + c) * 2 + 1];
        yr += arv * xr - aiv * xi;
        yi += arv * xi + aiv * xr;
    }
    if (m < 360) {
        size_t o = ((size_t)l * LM + m) * 32 + bC * 2;
        g_ysht[o]     = yr;
        g_ysht[o + 1] = yi;
    }
}

// ---------------- Legendre synthesis: parity fold, direct Fm writes ---------
__global__ void __launch_bounds__(256) k_syn(const float* __restrict__ leg)
{
    const int m  = blockIdx.x;
    const int jt = blockIdx.y;
    __shared__ float legs2[32][68];
    __shared__ float ys[32][36];
    const int tid = threadIdx.x;
    const int ty = tid >> 3, tx = tid & 7;
    float acc[2][2][4];
#pragma unroll
    for (int r = 0; r < 2; r++)
#pragma unroll
        for (int q = 0; q < 2; q++)
#pragma unroll
            for (int v = 0; v < 4; v++) acc[r][q][v] = 0.f;

    const int lstart = m & ~31;
    for (int l0 = lstart; l0 < 360; l0 += 32) {
#pragma unroll
        for (int p = 0; p < 8; p++) {
            int idx = tid + p * 256;
            int c = idx & 63, r = idx >> 6;
            int l = l0 + r, j = jt * 64 + c;
            legs2[r][c] = (l < 360 && j < NJ)
                        ? leg[((size_t)l * NH + m) * NH + j] : 0.f;
        }
#pragma unroll
        for (int p = 0; p < 4; p++) {
            int idx = tid + p * 256;
            int col = idx & 31, r = idx >> 5;
            int l = l0 + r;
            ys[r][col] = (l < 360) ? g_ysht[((size_t)l * LM + m) * 32 + col] : 0.f;
        }
        __syncthreads();
#pragma unroll 8
        for (int k = 0; k < 32; k++) {
            float4 yv = *(const float4*)&ys[k][4 * tx];
            float la = legs2[k][ty], lb = legs2[k][ty + 32];
            int q = k & 1;
            acc[0][q][0] += la * yv.x; acc[0][q][1] += la * yv.y;
            acc[0][q][2] += la * yv.z; acc[0][q][3] += la * yv.w;
            acc[1][q][0] += lb * yv.x; acc[1][q][1] += lb * yv.y;
            acc[1][q][2] += lb * yv.z; acc[1][q][3] += lb * yv.w;
        }
        __syncthreads();
    }
    const int pm = m & 1;
#pragma unroll
    for (int r = 0; r < 2; r++) {
        int j = jt * 64 + ty + 32 * r;
        if (j >= NJ) continue;
#pragma unroll
        for (int v = 0; v < 4; v++) {
            int col = 4 * tx + v;
            int bc = col >> 1, ri = col & 1;
            float se = acc[r][pm][v];
            float so = acc[r][1 - pm][v];
            size_t colm = (size_t)pm * KP + (m >> 1) + ri * 180;
            g_Fm[((size_t)(bc * 361 + j)) * FMLD + colm] = se + so;
            if (j < 180)
                g_Fm[((size_t)(bc * 361 + 360 - j)) * FMLD + colm] = se - so;
        }
    }
}

// ---------------- combine: unfold longitude + residual mean (float4) --------
__global__ void k_combine(float* __restrict__ out) {
    int i = blockIdx.x * 256 + threadIdx.x;
    if (i >= RR * 90) return;
    int r = i / 90, w = (i - r * 90) * 4;
    size_t si = (size_t)r * HW + w;
    float4 se = *(const float4*)&g_Se[si];
    float4 so = *(const float4*)&g_So[si];
    size_t o = (size_t)r * NW + w;
    float4 mu1 = *(const float4*)&g_xu[o];
    float4 mu2 = *(const float4*)&g_xu[o + 360];
    *(float4*)&out[o] = make_float4(se.x + so.x + mu1.x, se.y + so.y + mu1.y,
                                    se.z + so.z + mu1.z, se.w + so.w + mu1.w);
    *(float4*)&out[o + 360] = make_float4(se.x - so.x + mu2.x, se.y - so.y + mu2.y,
                                          se.z - so.z + mu2.z, se.w - so.w + mu2.w);
}

// ---------------- launch -----------------------------------------------------
extern "C" void kernel_launch(void* const* d_in, const int* in_sizes, int n_in,
                              void* d_out, int out_size) {
    const float* x = nullptr, *A = nullptr, *A_i = nullptr,
               *leg = nullptr, *wq = nullptr;
    for (int i = 0; i < n_in; i++) {
        int s = in_sizes[i];
        const float* p = (const float*)d_in[i];
        if (s == SZ_X)        x = p;
        else if (s == SZ_LEG) leg = p;
        else if (s == SZ_WQ)  wq = p;
        else if (s == SZ_A) { if (!A) A = p; else A_i = p; }
    }
    if (!x || !A || !A_i || !leg || !wq) {
        x = (const float*)d_in[0];  A = (const float*)d_in[1];
        A_i = (const float*)d_in[2]; leg = (const float*)d_in[3];
        wq = (const float*)d_in[4];
    }
    float* out = (float*)d_out;

    static bool attr_set = false;
    if (!attr_set) {
        cudaFuncSetAttribute(k_tmma_fwd, cudaFuncAttributeMaxDynamicSharedMemorySize, SMEMT);
        cudaFuncSetAttribute(k_tmma_inv, cudaFuncAttributeMaxDynamicSharedMemorySize, SMEMT);
        attr_set = true;
    }

    k_mean<<<(RR * 90 + 255) / 256, 256>>>(x);
    k_tables<<<(360 * 360 + 255) / 256, 256>>>();
    k_tmma_fwd<<<dim3(46, 3, 2), 256, SMEMT>>>();
    k_fold<<<(360 * NJ * 32 + 255) / 256, 256>>>(wq);
    k_ana<<<dim3(360, 3), 256>>>(leg);
    k_mix<<<dim3(360, 23), 256>>>(A, A_i);
    k_syn<<<dim3(360, 3), 256>>>(leg);
    k_split<<<(RR * 368 + 255) / 256, 256>>>();
    k_tmma_inv<<<dim3(3, 46, 2), 256, SMEMT>>>();
    k_combine<<<(RR * 90 + 255) / 256, 256>>>(out);

    (void)out_size;
}